// round 11
// baseline (speedup 1.0000x reference)
#include <cuda_runtime.h>
#include <cuda_fp16.h>
#include <cstdint>
#include <mma.h>

using namespace nvcuda;

#define S 4096
#define D 128
#define H 128
#define BATCH 2
#define KDIM 256
#define FEPS 1e-6f
#define FULLMASK 0xffffffffu

// ----------------------------- scratch (device globals: allocation-free) ---
__device__ __half g_Whi[4][KDIM][KDIM];
__device__ __half g_Wlo[4][KDIM][KDIM];     // UNSCALED residual: w - fp16(w)
__device__ float  g_beff[4][KDIM];
__device__ __half g_Q16[BATCH][S][KDIM];
__device__ __half g_K16[BATCH][S][KDIM];
__device__ __half g_V16[BATCH][S][KDIM];
__device__ float  g_Vf[BATCH][S][KDIM];
__device__ float  g_q2[BATCH][S];
__device__ float  g_k2[BATCH][S];
__device__ float  g_rowsum[BATCH][S];
__device__ float  g_cumV[BATCH][S][KDIM];
__device__ float  g_chunk[BATCH][64][KDIM];
__device__ float  g_estS[4][BATCH][S][KDIM];   // split-K slice outputs

// ----------------------------- helpers ------------------------------------
__device__ __forceinline__ uint32_t smem_u32(const void* p) {
    uint32_t a;
    asm("{ .reg .u64 t; cvta.to.shared.u64 t, %1; cvt.u32.u64 %0, t; }" : "=r"(a) : "l"(p));
    return a;
}
__device__ __forceinline__ void cp16(uint32_t dst, const void* src) {
    asm volatile("cp.async.ca.shared.global [%0], [%1], 16;" :: "r"(dst), "l"(src) : "memory");
}
#define CP_COMMIT() asm volatile("cp.async.commit_group;" ::: "memory")
#define CP_WAIT()   asm volatile("cp.async.wait_group 0;" ::: "memory")

// --------------------------------------------------------------------------
// Pack all 4 effective weights (fp16 hi + UNSCALED lo) + biases; zero q2/k2/rowsum.
__global__ void pack_all_kernel(
    const float* __restrict__ Wq_r, const float* __restrict__ Wq_i,
    const float* __restrict__ bq_r, const float* __restrict__ bq_i,
    const float* __restrict__ Wk_r, const float* __restrict__ Wk_i,
    const float* __restrict__ bk_r, const float* __restrict__ bk_i,
    const float* __restrict__ Wv_r, const float* __restrict__ Wv_i,
    const float* __restrict__ bv_r, const float* __restrict__ bv_i,
    const float* __restrict__ Wp_r, const float* __restrict__ Wp_i,
    const float* __restrict__ bp_r, const float* __restrict__ bp_i) {
    int p = blockIdx.y, k = blockIdx.x, j = threadIdx.x;
    const float *Wr, *Wi, *br, *bi;
    switch (p) {
        case 0:  Wr = Wq_r; Wi = Wq_i; br = bq_r; bi = bq_i; break;
        case 1:  Wr = Wk_r; Wi = Wk_i; br = bk_r; bi = bk_i; break;
        case 2:  Wr = Wv_r; Wi = Wv_i; br = bv_r; bi = bv_i; break;
        default: Wr = Wp_r; Wi = Wp_i; br = bp_r; bi = bp_i; break;
    }
    float w;
    if (j < 128) {
        w = (k < 128) ? Wr[j * D + k] : -Wi[j * D + (k - 128)];
    } else {
        int m = j - 128;
        w = (k < 128) ? Wi[m * D + k] : Wr[m * D + (k - 128)];
    }
    __half hi = __float2half(w);
    g_Whi[p][k][j] = hi;
    g_Wlo[p][k][j] = __float2half(w - __half2float(hi));   // unscaled residual
    if (k == 0) {
        g_beff[p][j] = (j < 128) ? (br[j] - bi[j]) : (br[j - 128] + bi[j - 128]);
    }
    if (p == 0 && k < 96) {
        int idx = k * 256 + j;                 // 0..24575
        if (idx < BATCH * S)          ((float*)g_q2)[idx] = 0.f;
        else if (idx < 2 * BATCH * S) ((float*)g_k2)[idx - BATCH * S] = 0.f;
        else                          ((float*)g_rowsum)[idx - 2 * BATCH * S] = 0.f;
    }
}

// --------------------------------------------------------------------------
// Projection GEMM: C[128 x 256] = A[128,256] x W[256,256] + bias.
// Block covers full N=256; warp tiles 64x64 (8 warps).
// PLAIN: A(hi) + full B resident. SPLIT: A hi/lo resident, B streamed in 4
// chunks of 64 K-rows (hi+lo); single fp32 accumulator (lo terms unscaled).
// MODE 0: A from Z planes; epilogue by p (Q16/K16 + q2/k2, or V16+Vf)
// MODE 1: A = sum of 4 g_estS slices; epilogue -> d_out complex mapping
#define PJ_STR 264
#define PJ_ALO 67584u                         // 128*264*2
#define PJ_SMEM 202752                        // 384*264*2

template <int MODE, bool SPLIT>
__device__ __forceinline__ void proj_body(const float* __restrict__ Abase,
                                          const __half* __restrict__ Wh,
                                          const __half* __restrict__ Wl,
                                          const float* __restrict__ bias,
                                          int b, int p, float* __restrict__ outp) {
    extern __shared__ __align__(16) char psm[];
    __half* Ahi = (__half*)psm;
    __half* Alo = (__half*)(psm + PJ_ALO);
    const uint32_t BH_OFF = SPLIT ? 135168u : 67584u;
    const uint32_t BL_OFF = 168960u;
    __half* Bh = (__half*)(psm + BH_OFF);
    __half* Bl = (__half*)(psm + BL_OFF);
    uint32_t sb = smem_u32(psm);
    int tid = threadIdx.x, lane = tid & 31, wid = tid >> 5;
    int wr = wid >> 2, wc = wid & 3;          // warp tile: rows wr*64, cols wc*64
    int s0 = blockIdx.y * 128;

    // kick off B prefetch (plain: all 256 K-rows; split: chunk 0 hi+lo)
    if (!SPLIT) {
#pragma unroll
        for (int it = 0; it < 32; it++) {
            int v = tid + it * 256, r = v >> 5, c8 = (v & 31) * 8;
            cp16(sb + BH_OFF + (uint32_t)(r * PJ_STR + c8) * 2, Wh + r * KDIM + c8);
        }
    } else {
#pragma unroll
        for (int it = 0; it < 8; it++) {
            int v = tid + it * 256, r = v >> 5, c8 = (v & 31) * 8;
            cp16(sb + BH_OFF + (uint32_t)(r * PJ_STR + c8) * 2, Wh + r * KDIM + c8);
            cp16(sb + BL_OFF + (uint32_t)(r * PJ_STR + c8) * 2, Wl + r * KDIM + c8);
        }
    }
    CP_COMMIT();

    // A load + fp16 split (hi + unscaled lo)
#pragma unroll
    for (int it = 0; it < 32; it++) {
        int v = tid + it * 256, r = v >> 6, c4 = (v & 63) * 4;
        float4 a;
        if (MODE == 0) {
            a = *(const float4*)(Abase + (size_t)(c4 >> 7) * (S * D)
                                       + (size_t)(s0 + r) * D + (c4 & 127));
        } else {
            const float* e = Abase + (size_t)(s0 + r) * KDIM + c4;
            const size_t SL = (size_t)BATCH * S * KDIM;
            float4 a0 = *(const float4*)(e);
            float4 a1 = *(const float4*)(e + SL);
            float4 a2 = *(const float4*)(e + 2 * SL);
            float4 a3 = *(const float4*)(e + 3 * SL);
            a.x = (a0.x + a1.x) + (a2.x + a3.x);
            a.y = (a0.y + a1.y) + (a2.y + a3.y);
            a.z = (a0.z + a1.z) + (a2.z + a3.z);
            a.w = (a0.w + a1.w) + (a2.w + a3.w);
        }
        __half h0 = __float2half(a.x), h1 = __float2half(a.y);
        __half h2 = __float2half(a.z), h3 = __float2half(a.w);
        int o = r * PJ_STR + c4;
        Ahi[o + 0] = h0; Ahi[o + 1] = h1; Ahi[o + 2] = h2; Ahi[o + 3] = h3;
        if (SPLIT) {
            Alo[o + 0] = __float2half(a.x - __half2float(h0));
            Alo[o + 1] = __float2half(a.y - __half2float(h1));
            Alo[o + 2] = __float2half(a.z - __half2float(h2));
            Alo[o + 3] = __float2half(a.w - __half2float(h3));
        }
    }
    CP_WAIT();
    __syncthreads();

    wmma::fragment<wmma::accumulator, 16, 16, 16, float> acc[4][4];
#pragma unroll
    for (int i = 0; i < 4; i++)
#pragma unroll
        for (int j = 0; j < 4; j++) wmma::fill_fragment(acc[i][j], 0.f);

    if (!SPLIT) {
#pragma unroll
        for (int ks = 0; ks < 16; ks++) {
            int k = ks * 16;
            wmma::fragment<wmma::matrix_a, 16, 16, 16, __half, wmma::row_major> a[4];
#pragma unroll
            for (int i = 0; i < 4; i++)
                wmma::load_matrix_sync(a[i], &Ahi[(wr * 64 + i * 16) * PJ_STR + k], PJ_STR);
#pragma unroll
            for (int j = 0; j < 4; j++) {
                wmma::fragment<wmma::matrix_b, 16, 16, 16, __half, wmma::row_major> bf;
                wmma::load_matrix_sync(bf, &Bh[k * PJ_STR + wc * 64 + j * 16], PJ_STR);
#pragma unroll
                for (int i = 0; i < 4; i++) wmma::mma_sync(acc[i][j], a[i], bf, acc[i][j]);
            }
        }
        __syncthreads();
    } else {
        for (int ch = 0; ch < 4; ch++) {
#pragma unroll
            for (int ks = 0; ks < 4; ks++) {
                int kA = ch * 64 + ks * 16, kB = ks * 16;
                wmma::fragment<wmma::matrix_a, 16, 16, 16, __half, wmma::row_major> ahi[4], alo[4];
#pragma unroll
                for (int i = 0; i < 4; i++) {
                    wmma::load_matrix_sync(ahi[i], &Ahi[(wr * 64 + i * 16) * PJ_STR + kA], PJ_STR);
                    wmma::load_matrix_sync(alo[i], &Alo[(wr * 64 + i * 16) * PJ_STR + kA], PJ_STR);
                }
#pragma unroll
                for (int j = 0; j < 4; j++) {
                    wmma::fragment<wmma::matrix_b, 16, 16, 16, __half, wmma::row_major> bh, bl;
                    wmma::load_matrix_sync(bh, &Bh[kB * PJ_STR + wc * 64 + j * 16], PJ_STR);
                    wmma::load_matrix_sync(bl, &Bl[kB * PJ_STR + wc * 64 + j * 16], PJ_STR);
#pragma unroll
                    for (int i = 0; i < 4; i++) {
                        wmma::mma_sync(acc[i][j], ahi[i], bh, acc[i][j]);
                        wmma::mma_sync(acc[i][j], ahi[i], bl, acc[i][j]);
                        wmma::mma_sync(acc[i][j], alo[i], bh, acc[i][j]);
                    }
                }
            }
            __syncthreads();
            if (ch < 3) {
                int kr = (ch + 1) * 64;
#pragma unroll
                for (int it = 0; it < 8; it++) {
                    int v = tid + it * 256, r = v >> 5, c8 = (v & 31) * 8;
                    cp16(sb + BH_OFF + (uint32_t)(r * PJ_STR + c8) * 2, Wh + (kr + r) * KDIM + c8);
                    cp16(sb + BL_OFF + (uint32_t)(r * PJ_STR + c8) * 2, Wl + (kr + r) * KDIM + c8);
                }
                CP_COMMIT();
                CP_WAIT();
                __syncthreads();
            }
        }
    }

    // epilogue: per-fragment staging at smem base (A region free after syncs)
    float* stage = (float*)psm + wid * (16 * 20);
#pragma unroll
    for (int i = 0; i < 4; i++) {
        float sq = 0.f;
#pragma unroll
        for (int j = 0; j < 4; j++) {
            wmma::store_matrix_sync(stage, acc[i][j], 20, wmma::mem_row_major);
            __syncwarp();
            int row = lane >> 1, colh = lane & 1;
            int s = s0 + wr * 64 + i * 16 + row;
            int jb = wc * 64 + j * 16 + colh * 8;
#pragma unroll
            for (int c = 0; c < 8; c++) {
                int jj = jb + c;
                float v = stage[row * 20 + colh * 8 + c] + bias[jj];
                if (MODE == 0) {
                    __half h = __float2half(v);
                    if (p == 0)      { g_Q16[b][s][jj] = h; sq += v * v; }
                    else if (p == 1) { g_K16[b][s][jj] = h; sq += v * v; }
                    else             { g_V16[b][s][jj] = h; g_Vf[b][s][jj] = v; }
                } else {
                    outp[((size_t)(b * 2 + (jj >> 7)) * S + s) * H + (jj & 127)] = v;
                }
            }
            __syncwarp();
        }
        if (MODE == 0 && p < 2) {
            sq += __shfl_xor_sync(FULLMASK, sq, 1);
            if ((lane & 1) == 0) {
                int s = s0 + wr * 64 + i * 16 + (lane >> 1);
                if (p == 0) atomicAdd(&g_q2[b][s], sq);
                else        atomicAdd(&g_k2[b][s], sq);
            }
        }
    }
}

__global__ __launch_bounds__(256, 1) void projQK_kernel(const float* __restrict__ Zq,
                                                        const float* __restrict__ Zk) {
    int z = blockIdx.z;
    int b = z >> 1, p = z & 1;
    const float* Zb = ((p == 0) ? Zq : Zk) + (size_t)b * 2 * S * D;
    proj_body<0, false>(Zb, &g_Whi[p][0][0], nullptr, g_beff[p], b, p, nullptr);
}

__global__ __launch_bounds__(256, 1) void projV_kernel(const float* __restrict__ Zv) {
    int b = blockIdx.z;
    proj_body<0, true>(Zv + (size_t)b * 2 * S * D, &g_Whi[2][0][0], &g_Wlo[2][0][0],
                       g_beff[2], b, 2, nullptr);
}

__global__ __launch_bounds__(256, 1) void outproj_kernel(float* __restrict__ out) {
    int b = blockIdx.z;
    proj_body<1, true>(&g_estS[0][b][0][0], &g_Whi[3][0][0], &g_Wlo[3][0][0],
                       g_beff[3], b, 0, out);
}

// --------------------------------------------------------------------------
// Hierarchical prefix sum of V over t (64 chunks of 64 rows; coalesced)
__global__ __launch_bounds__(256) void prefix1_kernel() {
    int ch = blockIdx.x, b = blockIdx.y, col = threadIdx.x;
    const float* V = &g_Vf[b][ch * 64][0];
    float s = 0.f;
#pragma unroll 8
    for (int r = 0; r < 64; r++) s += V[(size_t)r * KDIM + col];
    g_chunk[b][ch][col] = s;
}

__global__ __launch_bounds__(256) void prefix3_kernel() {
    int ch = blockIdx.x, b = blockIdx.y, col = threadIdx.x;
    float c = 0.f;
    for (int c2 = 0; c2 < ch; c2++) c += g_chunk[b][c2][col];
    const float* V = &g_Vf[b][ch * 64][0];
    float* C = &g_cumV[b][ch * 64][0];
#pragma unroll 4
    for (int r = 0; r < 64; r++) {
        c += V[(size_t)r * KDIM + col];
        C[(size_t)r * KDIM + col] = c;
    }
}

// --------------------------------------------------------------------------
// Logits+exp: block tile 128(M)x256(N), full K=256 resident, warp tile 64x64.
#define LOG_ASTRIDE 264
#define LOG_AOFF 0
#define LOG_BOFF (128 * LOG_ASTRIDE * 2)            // 67584
#define LOG_SMEM (LOG_BOFF + 256 * LOG_ASTRIDE * 2) // 202752

__global__ __launch_bounds__(256) void logits_kernel(const float* __restrict__ nf_,
                                                     const float* __restrict__ tau_,
                                                     float* __restrict__ attn) {
    int jN = blockIdx.x, iT = blockIdx.y, b = blockIdx.z;
    int s0 = iT * 128, t0 = jN * 256;
    int tid = threadIdx.x, lane = tid & 31, wid = tid >> 5;

    if (2 * jN > iT) {   // entire tile above diagonal: zero-fill
        float4 z = make_float4(0.f, 0.f, 0.f, 0.f);
#pragma unroll
        for (int it = 0; it < 32; it++) {
            int f = it * 256 + tid;
            int r = f >> 6, c4 = (f & 63) * 4;
            *(float4*)&attn[((size_t)(b * S + s0 + r)) * S + t0 + c4] = z;
        }
        return;
    }

    extern __shared__ __align__(16) char smem[];
    __half* Ash = (__half*)(smem + LOG_AOFF);
    __half* Bsh = (__half*)(smem + LOG_BOFF);
    uint32_t aBase = smem_u32(smem);

#pragma unroll
    for (int it = 0; it < 16; it++) {
        int v = tid + it * 256;
        int r = v >> 5, c8 = (v & 31) * 8;
        cp16(aBase + LOG_AOFF + (uint32_t)(r * LOG_ASTRIDE + c8) * 2,
             &g_Q16[b][s0 + r][c8]);
    }
#pragma unroll
    for (int it = 0; it < 32; it++) {
        int v = tid + it * 256;
        int r = v >> 5, c8 = (v & 31) * 8;
        cp16(aBase + LOG_BOFF + (uint32_t)(r * LOG_ASTRIDE + c8) * 2,
             &g_K16[b][t0 + r][c8]);
    }
    CP_COMMIT();
    CP_WAIT();
    __syncthreads();

    int wr = wid >> 2, wc = wid & 3;
    wmma::fragment<wmma::accumulator, 16, 16, 16, float> acc[4][4];
#pragma unroll
    for (int i = 0; i < 4; i++)
#pragma unroll
        for (int j = 0; j < 4; j++) wmma::fill_fragment(acc[i][j], 0.f);

#pragma unroll
    for (int ks = 0; ks < 16; ks++) {
        int k = ks * 16;
        wmma::fragment<wmma::matrix_a, 16, 16, 16, __half, wmma::row_major> a[4];
#pragma unroll
        for (int i = 0; i < 4; i++)
            wmma::load_matrix_sync(a[i], &Ash[(wr * 64 + i * 16) * LOG_ASTRIDE + k], LOG_ASTRIDE);
#pragma unroll
        for (int j = 0; j < 4; j++) {
            wmma::fragment<wmma::matrix_b, 16, 16, 16, __half, wmma::col_major> bf;
            wmma::load_matrix_sync(bf, &Bsh[(wc * 64 + j * 16) * LOG_ASTRIDE + k], LOG_ASTRIDE);
#pragma unroll
            for (int i = 0; i < 4; i++) wmma::mma_sync(acc[i][j], a[i], bf, acc[i][j]);
        }
    }

    __syncthreads();

    float* st = (float*)smem + wid * 64 * 68;
#pragma unroll
    for (int i = 0; i < 4; i++)
#pragma unroll
        for (int j = 0; j < 4; j++)
            wmma::store_matrix_sync(&st[(i * 16) * 68 + j * 16], acc[i][j], 68,
                                    wmma::mem_row_major);
    __syncwarp();

    float tv = tau_[0];
    float sp = (tv > 20.f) ? tv : log1pf(__expf(tv));
    float coeff = -sp * 0.08838834764831845f;
    float nf = nf_[0];
    float nf2 = nf * nf + FEPS;

#pragma unroll
    for (int rr = 0; rr < 2; rr++) {
        int row = lane + rr * 32;
        int s = s0 + wr * 64 + row;
        float q2s = g_q2[b][s];
        size_t rowbase = ((size_t)(b * S + s)) * S;
        float esum = 0.f;
#pragma unroll
        for (int c4 = 0; c4 < 16; c4++) {
            int t = t0 + wc * 64 + c4 * 4;
            float4 re = *(float4*)&st[row * 68 + c4 * 4];
            float4 o;
            o.x = __expf(coeff * __logf(nf2 + q2s + g_k2[b][t + 0] - 2.f * re.x));
            o.y = __expf(coeff * __logf(nf2 + q2s + g_k2[b][t + 1] - 2.f * re.y));
            o.z = __expf(coeff * __logf(nf2 + q2s + g_k2[b][t + 2] - 2.f * re.z));
            o.w = __expf(coeff * __logf(nf2 + q2s + g_k2[b][t + 3] - 2.f * re.w));
            if (t + 0 > s) o.x = 0.f;
            if (t + 1 > s) o.y = 0.f;
            if (t + 2 > s) o.z = 0.f;
            if (t + 3 > s) o.w = 0.f;
            esum += (o.x + o.y) + (o.z + o.w);
            *(float4*)&attn[rowbase + t] = o;
        }
        atomicAdd(&g_rowsum[b][s], esum);
    }
}

// --------------------------------------------------------------------------
// Normalize: w = e / rowsum (streamed, in place)
__global__ __launch_bounds__(128) void normalize_kernel(float* __restrict__ attn) {
    int s = blockIdx.x, b = blockIdx.y;
    int tid = threadIdx.x;
    float inv = 1.f / g_rowsum[b][s];
    int kend = ((s >> 7) + 1) << 7;
    float* L = attn + ((size_t)(b * S + s)) * S;
    for (int i = tid * 4; i < kend; i += 512) {
        float4 e = *(float4*)&L[i];
        *(float4*)&L[i] = make_float4(e.x * inv, e.y * inv, e.z * inv, e.w * inv);
    }
}

// --------------------------------------------------------------------------
// pv: estS[slice] = (dev @ V16)/1024 (+ cumV/(s+1) on slice 0)
// dev built on the fly from attn; 4 split-K slices, plain stores (no atomics).
struct PvSmem {
    union {
        __half A[64][72];
        float  stage[8][16][20];
    } uA;
    __half Bm[64][264];
};

__global__ __launch_bounds__(256) void pv_kernel(const float* __restrict__ attn) {
    int slice = blockIdx.x, mT = blockIdx.y, b = blockIdx.z;
    int s0 = mT * 64;
    int nchunks = mT + 1;
    int c_lo = (slice * nchunks) >> 2;
    int c_hi = ((slice + 1) * nchunks) >> 2;

    __shared__ __align__(16) PvSmem sm;
    int tid = threadIdx.x, lane = tid & 31, wid = tid >> 5;
    int wr = wid >> 2, wc = wid & 3;
    uint32_t bBase = smem_u32(&sm.Bm[0][0]);

    wmma::fragment<wmma::accumulator, 16, 16, 16, float> acc[2][4];
#pragma unroll
    for (int i = 0; i < 2; i++)
#pragma unroll
        for (int j = 0; j < 4; j++) wmma::fill_fragment(acc[i][j], 0.f);

    for (int ch = c_lo; ch < c_hi; ch++) {
        int k0 = ch * 64;
#pragma unroll
        for (int it = 0; it < 4; it++) {
            int v = tid + it * 256;
            int r = v >> 4, c4 = (v & 15) * 4;
            int s = s0 + r;
            float crow = 1.f / (float)(s + 1);
            int gcol = k0 + c4;
            float4 w4 = *(const float4*)&attn[((size_t)(b * S + s)) * S + gcol];
            float p0 = (gcol + 0 <= s) ? (w4.x - crow) * 1024.f : 0.f;
            float p1 = (gcol + 1 <= s) ? (w4.y - crow) * 1024.f : 0.f;
            float p2 = (gcol + 2 <= s) ? (w4.z - crow) * 1024.f : 0.f;
            float p3 = (gcol + 3 <= s) ? (w4.w - crow) * 1024.f : 0.f;
            *(__half2*)&sm.uA.A[r][c4]     = __floats2half2_rn(p0, p1);
            *(__half2*)&sm.uA.A[r][c4 + 2] = __floats2half2_rn(p2, p3);
        }
#pragma unroll
        for (int it = 0; it < 8; it++) {
            int v = tid + it * 256;
            int r = v >> 5, c8 = (v & 31) * 8;
            cp16(bBase + (uint32_t)(r * 264 + c8) * 2, &g_V16[b][k0 + r][c8]);
        }
        CP_COMMIT();
        CP_WAIT();
        __syncthreads();
#pragma unroll
        for (int ks = 0; ks < 4; ks++) {
            int k = ks * 16;
            wmma::fragment<wmma::matrix_a, 16, 16, 16, __half, wmma::row_major> a[2];
#pragma unroll
            for (int i = 0; i < 2; i++)
                wmma::load_matrix_sync(a[i], &sm.uA.A[wr * 32 + i * 16][k], 72);
#pragma unroll
            for (int j = 0; j < 4; j++) {
                wmma::fragment<wmma::matrix_b, 16, 16, 16, __half, wmma::row_major> bf;
                wmma::load_matrix_sync(bf, &sm.Bm[k][wc * 64 + j * 16], 264);
#pragma unroll
                for (int i = 0; i < 2; i++) wmma::mma_sync(acc[i][j], a[i], bf, acc[i][j]);
            }
        }
        __syncthreads();
    }

    // epilogue: plain stores into this slice's private buffer
#pragma unroll
    for (int i = 0; i < 2; i++) {
#pragma unroll
        for (int j = 0; j < 4; j++) {
            wmma::store_matrix_sync(&sm.uA.stage[wid][0][0], acc[i][j], 20,
                                    wmma::mem_row_major);
            __syncwarp();
            int row = lane >> 1, colh = lane & 1;
            int s = s0 + wr * 32 + i * 16 + row;
            float invn = 1.f / (float)(s + 1);
            int nb = wc * 64 + j * 16 + colh * 8;
#pragma unroll
            for (int c = 0; c < 8; c++) {
                int col = nb + c;
                float v = sm.uA.stage[wid][row][colh * 8 + c] * (1.f / 1024.f);
                if (slice == 0) v += g_cumV[b][s][col] * invn;
                g_estS[slice][b][s][col] = v;
            }
            __syncwarp();
        }
    }
}

// --------------------------------------------------------------------------
extern "C" void kernel_launch(void* const* d_in, const int* in_sizes, int n_in,
                              void* d_out, int out_size) {
    (void)in_sizes; (void)n_in; (void)out_size;
    const float* Zq  = (const float*)d_in[0];
    const float* Zk  = (const float*)d_in[1];
    const float* Zv  = (const float*)d_in[2];
    const float* nf  = (const float*)d_in[19];
    const float* tau = (const float*)d_in[20];
    float* out  = (float*)d_out;                    // (B,2,S,H,1)
    float* attn = out + (size_t)BATCH * 2 * S * H;  // (B,S,S)

    cudaFuncSetAttribute(logits_kernel, cudaFuncAttributeMaxDynamicSharedMemorySize, LOG_SMEM);
    cudaFuncSetAttribute(projQK_kernel, cudaFuncAttributeMaxDynamicSharedMemorySize, PJ_SMEM);
    cudaFuncSetAttribute(projV_kernel, cudaFuncAttributeMaxDynamicSharedMemorySize, PJ_SMEM);
    cudaFuncSetAttribute(outproj_kernel, cudaFuncAttributeMaxDynamicSharedMemorySize, PJ_SMEM);

    pack_all_kernel<<<dim3(256, 4), 256>>>(
        (const float*)d_in[3],  (const float*)d_in[4],  (const float*)d_in[5],  (const float*)d_in[6],
        (const float*)d_in[7],  (const float*)d_in[8],  (const float*)d_in[9],  (const float*)d_in[10],
        (const float*)d_in[11], (const float*)d_in[12], (const float*)d_in[13], (const float*)d_in[14],
        (const float*)d_in[15], (const float*)d_in[16], (const float*)d_in[17], (const float*)d_in[18]);

    projQK_kernel<<<dim3(1, 32, 4), 256, PJ_SMEM>>>(Zq, Zk);
    projV_kernel<<<dim3(1, 32, BATCH), 256, PJ_SMEM>>>(Zv);
    prefix1_kernel<<<dim3(64, BATCH), 256>>>();
    prefix3_kernel<<<dim3(64, BATCH), 256>>>();
    logits_kernel<<<dim3(16, 32, BATCH), 256, LOG_SMEM>>>(nf, tau, attn);
    normalize_kernel<<<dim3(S, BATCH), 128>>>(attn);
    pv_kernel<<<dim3(4, 64, BATCH), 256>>>(attn);
    outproj_kernel<<<dim3(1, 32, BATCH), 256, PJ_SMEM>>>(out);
}